// round 16
// baseline (speedup 1.0000x reference)
#include <cuda_runtime.h>
#include <cuda_bf16.h>
#include <cstdint>

constexpr int S = 2048, D = 64;
constexpr int BH = 32;
constexpr float SCALE = 0.125f;
constexpr size_t CTX_ELEMS = (size_t)BH * S * D;

__device__ float g_m[BH * S];
__device__ float g_l[BH * S];

// ---- bf16 split helpers ----
__device__ __forceinline__ uint32_t bf2pack(float a, float b) {
    __nv_bfloat162 t = __floats2bfloat162_rn(a, b);
    return *reinterpret_cast<uint32_t*>(&t);
}
__device__ __forceinline__ float bfres(float a) {
    return a - __bfloat162float(__float2bfloat16(a));
}

// ---- smem addressing ----
__device__ __forceinline__ uint32_t smem_u32(const void* p) {
    uint32_t a;
    asm("{ .reg .u64 t; cvta.to.shared.u64 t, %1; cvt.u32.u64 %0, t; }" : "=r"(a) : "l"(p));
    return a;
}
__device__ __forceinline__ uint32_t sw128(uint32_t off) { return off ^ ((off >> 3) & 0x70); }

// ---- ldmatrix / mma wrappers ----
__device__ __forceinline__ void ldsm_x4(uint32_t* r, uint32_t addr) {
    asm volatile("ldmatrix.sync.aligned.m8n8.x4.shared.b16 {%0,%1,%2,%3}, [%4];"
                 : "=r"(r[0]), "=r"(r[1]), "=r"(r[2]), "=r"(r[3]) : "r"(addr));
}
__device__ __forceinline__ void ldsm_x2(uint32_t* r, uint32_t addr) {
    asm volatile("ldmatrix.sync.aligned.m8n8.x2.shared.b16 {%0,%1}, [%2];"
                 : "=r"(r[0]), "=r"(r[1]) : "r"(addr));
}
__device__ __forceinline__ void ldsm_x2t(uint32_t* r, uint32_t addr) {
    asm volatile("ldmatrix.sync.aligned.m8n8.x2.trans.shared.b16 {%0,%1}, [%2];"
                 : "=r"(r[0]), "=r"(r[1]) : "r"(addr));
}
__device__ __forceinline__ void mma_bf16(float* d, const uint32_t* a, const uint32_t* b) {
    asm volatile(
        "mma.sync.aligned.m16n8k16.row.col.f32.bf16.bf16.f32 "
        "{%0,%1,%2,%3}, {%4,%5,%6,%7}, {%8,%9}, {%0,%1,%2,%3};"
        : "+f"(d[0]), "+f"(d[1]), "+f"(d[2]), "+f"(d[3])
        : "r"(a[0]), "r"(a[1]), "r"(a[2]), "r"(a[3]), "r"(b[0]), "r"(b[1]));
}

// pass1 smem (bytes): 4 tiles of 128 x 64 bf16 (128B rows, SW128)
constexpr int TILE_B = 128 * 128;
constexpr int SM_QHI = 0;
constexpr int SM_QLO = TILE_B;
constexpr int SM_KHI = 2 * TILE_B;
constexpr int SM_KLO = 3 * TILE_B;
constexpr int SM1_TOTAL = 4 * TILE_B;   // 65536 B

// pass2 smem: 2 stages of {PHI 16K, PLO 16K, VHI 8K, VLO 8K} = 48K each
constexpr int ST_PHI = 0;
constexpr int ST_PLO = 16384;
constexpr int ST_VHI = 32768;
constexpr int ST_VLO = 40960;
constexpr int STAGE_B = 49152;
constexpr int SM2_TOTAL = 2 * STAGE_B;  // 98304 B

// ---------------------------------------------------------------------------
// Pass 1 (HMMA, unchanged passing version): scores -> SC; m/l; zero-fill.
// ---------------------------------------------------------------------------
__global__ void __launch_bounds__(128, 2)
attn_pass1(const float* __restrict__ Q, const float* __restrict__ K,
           float* __restrict__ SC)
{
    extern __shared__ char smem[];
    const uint32_t sb = smem_u32(smem);

    const int tid = threadIdx.x;
    const int lane = tid & 31;
    const int warp = tid >> 5;
    const int pid = blockIdx.x;
    const int bh = blockIdx.y;

    {
        const float4 z = make_float4(0.f, 0.f, 0.f, 0.f);
#pragma unroll
        for (int half = 0; half < 2; ++half) {
            const int qt = half ? (15 - pid) : pid;
            const int c0 = (qt + 1) * 128;
            if (c0 < S) {
                const int w4 = (S - c0) >> 2;
                const int r0 = qt * 128;
                for (int i = tid; i < 128 * w4; i += 128) {
                    const int row = i / w4;
                    const int c4 = i - row * w4;
                    *((float4*)(SC + ((size_t)bh * S + r0 + row) * S + c0 + 4 * c4)) = z;
                }
            }
        }
    }

    for (int half = 0; half < 2; ++half) {
        const int qt = half ? (15 - pid) : pid;
        const int r0 = qt * 128;

        __syncthreads();
        {
            const float* qbase = Q + ((size_t)bh * S + r0) * D;
            for (int i = tid; i < 128 * 16; i += 128) {
                int row = i >> 4, c4 = i & 15;
                float4 v = ((const float4*)(qbase + row * D))[c4];
                uint32_t off = sw128((uint32_t)(row * 128 + c4 * 8));
                *((uint2*)(smem + SM_QHI + off)) =
                    make_uint2(bf2pack(v.x, v.y), bf2pack(v.z, v.w));
                *((uint2*)(smem + SM_QLO + off)) =
                    make_uint2(bf2pack(bfres(v.x), bfres(v.y)), bf2pack(bfres(v.z), bfres(v.w)));
            }
        }

        float m[2][2], l[2][2];
#pragma unroll
        for (int a = 0; a < 2; a++)
#pragma unroll
            for (int b = 0; b < 2; b++) { m[a][b] = -1e30f; l[a][b] = 0.0f; }

        for (int kt = 0; kt <= qt; ++kt) {
            __syncthreads();
            {
                const float* kbase = K + ((size_t)bh * S + kt * 128) * D;
                for (int i = tid; i < 128 * 16; i += 128) {
                    int row = i >> 4, c4 = i & 15;
                    float4 v = ((const float4*)(kbase + row * D))[c4];
                    uint32_t off = sw128((uint32_t)(row * 128 + c4 * 8));
                    *((uint2*)(smem + SM_KHI + off)) =
                        make_uint2(bf2pack(v.x, v.y), bf2pack(v.z, v.w));
                    *((uint2*)(smem + SM_KLO + off)) =
                        make_uint2(bf2pack(bfres(v.x), bfres(v.y)),
                                   bf2pack(bfres(v.z), bfres(v.w)));
                }
            }
            __syncthreads();

            float acc[2][16][4];
#pragma unroll
            for (int mb = 0; mb < 2; mb++)
#pragma unroll
                for (int j = 0; j < 16; j++)
#pragma unroll
                    for (int x = 0; x < 4; x++) acc[mb][j][x] = 0.0f;

#pragma unroll
            for (int p = 0; p < 3; ++p) {
                const uint32_t abase = sb + ((p == 2) ? SM_QLO : SM_QHI);
                const uint32_t bbase = sb + ((p == 1) ? SM_KLO : SM_KHI);
#pragma unroll
                for (int ks = 0; ks < 4; ++ks) {
                    const int kk = 16 * ks;
                    uint32_t afrag[2][4];
#pragma unroll
                    for (int mb = 0; mb < 2; mb++) {
                        const int arow = warp * 32 + mb * 16 + (lane & 7) + ((lane >> 3) & 1) * 8;
                        const uint32_t acol = (uint32_t)(kk * 2) + (uint32_t)(lane >> 4) * 16u;
                        ldsm_x4(afrag[mb], abase + sw128((uint32_t)(arow * 128) + acol));
                    }
#pragma unroll
                    for (int j = 0; j < 16; ++j) {
                        const int brow = 8 * j + (lane & 7);
                        const uint32_t bcol = (uint32_t)(kk * 2) + ((uint32_t)(lane >> 3) & 1u) * 16u;
                        uint32_t bfrag[2];
                        ldsm_x2(bfrag, bbase + sw128((uint32_t)(brow * 128) + bcol));
                        mma_bf16(acc[0][j], afrag[0], bfrag);
                        mma_bf16(acc[1][j], afrag[1], bfrag);
                    }
                }
            }

            const bool diag = (kt == qt);
#pragma unroll
            for (int mb = 0; mb < 2; mb++) {
#pragma unroll
                for (int rg = 0; rg < 2; rg++) {
                    const int row = warp * 32 + mb * 16 + rg * 8 + (lane >> 2);
                    float sv[32];
                    float mx = -1e30f;
#pragma unroll
                    for (int j = 0; j < 16; j++) {
                        const int c0 = 8 * j + (lane & 3) * 2;
                        float s0 = acc[mb][j][2 * rg] * SCALE;
                        float s1 = acc[mb][j][2 * rg + 1] * SCALE;
                        if (diag) {
                            if (c0 > row) s0 = -1e9f;
                            if (c0 + 1 > row) s1 = -1e9f;
                        }
                        sv[2 * j] = s0;
                        sv[2 * j + 1] = s1;
                        mx = fmaxf(mx, fmaxf(s0, s1));
                    }
                    mx = fmaxf(mx, __shfl_xor_sync(0xffffffffu, mx, 1));
                    mx = fmaxf(mx, __shfl_xor_sync(0xffffffffu, mx, 2));

                    const float mn = fmaxf(m[mb][rg], mx);
                    float ps = 0.0f;
#pragma unroll
                    for (int c = 0; c < 32; c++) ps += __expf(sv[c] - mn);
                    ps += __shfl_xor_sync(0xffffffffu, ps, 1);
                    ps += __shfl_xor_sync(0xffffffffu, ps, 2);

                    l[mb][rg] = l[mb][rg] * __expf(m[mb][rg] - mn) + ps;
                    m[mb][rg] = mn;

                    float* dst = SC + ((size_t)bh * S + r0 + row) * S + kt * 128;
#pragma unroll
                    for (int j = 0; j < 16; j++)
                        *((float2*)(dst + 8 * j + (lane & 3) * 2)) =
                            make_float2(sv[2 * j], sv[2 * j + 1]);
                }
            }
        }

        if ((lane & 3) == 0) {
#pragma unroll
            for (int mb = 0; mb < 2; mb++)
#pragma unroll
                for (int rg = 0; rg < 2; rg++) {
                    const int row = warp * 32 + mb * 16 + rg * 8 + (lane >> 2);
                    g_m[bh * S + r0 + row] = m[mb][rg];
                    g_l[bh * S + r0 + row] = l[mb][rg];
                }
        }
    }
}

// ---------------------------------------------------------------------------
// Pass 2 (HMMA PV, double-buffered TK=64 stages, 1 sync/tile):
// probs -> gmem + bf16 hi/lo smem; ctx via MMA fragments.
// 256 threads = 8 warps in 4m x 2n grid (warp: 32 rows x 32 d).
// ---------------------------------------------------------------------------
__global__ void __launch_bounds__(256, 2)
attn_pass2(const float* __restrict__ V, float* __restrict__ SC,
           float* __restrict__ CTX)
{
    extern __shared__ char sm2[];
    const uint32_t sb = smem_u32(sm2);

    const int tid = threadIdx.x;
    const int lane = tid & 31;
    const int warp = tid >> 5;
    const int wm = warp & 3;          // m quarter (32 rows)
    const int wn = warp >> 2;         // n half (32 d)
    const int prow = tid >> 1;        // prob row 0..127
    const int pcb = (tid & 1) * 64;   // prob col offset in BYTES within 128B row
    const int pid = blockIdx.x;
    const int bh = blockIdx.y;

    for (int half = 0; half < 2; ++half) {
        const int qt = half ? (15 - pid) : pid;
        const int r0 = qt * 128;
        const int nt = 2 * (qt + 1);

        const float mrow = g_m[bh * S + r0 + prow];
        const float rlrow = 1.0f / g_l[bh * S + r0 + prow];

        float cacc[2][4][4];
#pragma unroll
        for (int mb = 0; mb < 2; mb++)
#pragma unroll
            for (int j = 0; j < 4; j++)
#pragma unroll
                for (int x = 0; x < 4; x++) cacc[mb][j][x] = 0.0f;

        // ---- fill(kt): V + probs into stage kt&1 ----
#define FILL_STAGE(ktf)                                                         \
        do {                                                                    \
            char* base = sm2 + ((ktf) & 1) * STAGE_B;                           \
            const float* vbase = V + ((size_t)bh * S + (ktf) * 64) * D;         \
            for (int i = tid; i < 64 * 16; i += 256) {                          \
                int row = i >> 4, c4 = i & 15;                                  \
                float4 v = ((const float4*)(vbase + row * D))[c4];              \
                uint32_t off = sw128((uint32_t)(row * 128 + c4 * 8));           \
                *((uint2*)(base + ST_VHI + off)) =                              \
                    make_uint2(bf2pack(v.x, v.y), bf2pack(v.z, v.w));           \
                *((uint2*)(base + ST_VLO + off)) =                              \
                    make_uint2(bf2pack(bfres(v.x), bfres(v.y)),                 \
                               bf2pack(bfres(v.z), bfres(v.w)));                \
            }                                                                   \
            float* srow = SC + ((size_t)bh * S + r0 + prow) * S + (ktf) * 64 + (pcb >> 1); \
            _Pragma("unroll")                                                   \
            for (int c4 = 0; c4 < 8; ++c4) {                                    \
                float4 s4 = ((const float4*)srow)[c4];                          \
                float4 p4;                                                      \
                p4.x = __expf(s4.x - mrow) * rlrow;                             \
                p4.y = __expf(s4.y - mrow) * rlrow;                             \
                p4.z = __expf(s4.z - mrow) * rlrow;                             \
                p4.w = __expf(s4.w - mrow) * rlrow;                             \
                ((float4*)srow)[c4] = p4;                                       \
                uint32_t off = sw128((uint32_t)(prow * 128 + pcb + c4 * 8));    \
                *((uint2*)(base + ST_PHI + off)) =                              \
                    make_uint2(bf2pack(p4.x, p4.y), bf2pack(p4.z, p4.w));       \
                *((uint2*)(base + ST_PLO + off)) =                              \
                    make_uint2(bf2pack(bfres(p4.x), bfres(p4.y)),               \
                               bf2pack(bfres(p4.z), bfres(p4.w)));              \
            }                                                                   \
        } while (0)

        FILL_STAGE(0);
        __syncthreads();

        for (int kt = 0; kt < nt; ++kt) {
            if (kt + 1 < nt) FILL_STAGE(kt + 1);

            // MMA on stage kt&1
            {
                const uint32_t base = sb + (kt & 1) * STAGE_B;
#pragma unroll
                for (int ks = 0; ks < 4; ++ks) {
                    uint32_t aPhi[2][4], aPlo[2][4];
#pragma unroll
                    for (int mb = 0; mb < 2; mb++) {
                        const int arow = wm * 32 + mb * 16 + (lane & 7) + ((lane >> 3) & 1) * 8;
                        const uint32_t aoff =
                            sw128((uint32_t)(arow * 128) + (uint32_t)(ks * 32) + (uint32_t)(lane >> 4) * 16u);
                        ldsm_x4(aPhi[mb], base + ST_PHI + aoff);
                        ldsm_x4(aPlo[mb], base + ST_PLO + aoff);
                    }
                    const int brow = ks * 16 + (lane & 7) + ((lane >> 3) & 1) * 8;
#pragma unroll
                    for (int j = 0; j < 4; ++j) {
                        const uint32_t boff =
                            sw128((uint32_t)(brow * 128) + (uint32_t)(wn * 64 + j * 16));
                        uint32_t bhi[2], blo[2];
                        ldsm_x2t(bhi, base + ST_VHI + boff);
                        ldsm_x2t(blo, base + ST_VLO + boff);
#pragma unroll
                        for (int mb = 0; mb < 2; mb++) {
                            mma_bf16(cacc[mb][j], aPhi[mb], bhi);
                            mma_bf16(cacc[mb][j], aPlo[mb], bhi);
                            mma_bf16(cacc[mb][j], aPhi[mb], blo);
                        }
                    }
                }
            }
            __syncthreads();
        }

        // Write context: warp rows wm*32 + mb*16 + rg*8 + lane>>2, cols wn*32 + j*8
#pragma unroll
        for (int mb = 0; mb < 2; mb++)
#pragma unroll
            for (int rg = 0; rg < 2; rg++) {
                const int row = wm * 32 + mb * 16 + rg * 8 + (lane >> 2);
                float* crow = CTX + ((size_t)bh * S + r0 + row) * D + wn * 32;
#pragma unroll
                for (int j = 0; j < 4; j++)
                    *((float2*)(crow + j * 8 + (lane & 3) * 2)) =
                        make_float2(cacc[mb][j][2 * rg], cacc[mb][j][2 * rg + 1]);
            }
#undef FILL_STAGE
    }
}

// ---------------------------------------------------------------------------
extern "C" void kernel_launch(void* const* d_in, const int* in_sizes, int n_in,
                              void* d_out, int out_size)
{
    const float* q = (const float*)d_in[0];
    const float* k = (const float*)d_in[1];
    const float* v = (const float*)d_in[2];

    float* out = (float*)d_out;
    float* ctx = out;                 // [BH, S, D]
    float* sc  = out + CTX_ELEMS;     // [BH, S, S]

    cudaFuncSetAttribute(attn_pass1, cudaFuncAttributeMaxDynamicSharedMemorySize, SM1_TOTAL);
    cudaFuncSetAttribute(attn_pass2, cudaFuncAttributeMaxDynamicSharedMemorySize, SM2_TOTAL);

    attn_pass1<<<dim3(8, BH), 128, SM1_TOTAL>>>(q, k, sc);
    attn_pass2<<<dim3(8, BH), 256, SM2_TOTAL>>>(v, sc, ctx);
}

// round 17
// speedup vs baseline: 1.4279x; 1.4279x over previous
#include <cuda_runtime.h>
#include <cuda_bf16.h>
#include <cstdint>

constexpr int S = 2048, D = 64;
constexpr int BH = 32;
constexpr float SCALE = 0.125f;
constexpr size_t CTX_ELEMS = (size_t)BH * S * D;

__device__ float g_m[BH * S];
__device__ float g_l[BH * S];

// ---- bf16 split helpers ----
__device__ __forceinline__ uint32_t bf2pack(float a, float b) {
    __nv_bfloat162 t = __floats2bfloat162_rn(a, b);
    return *reinterpret_cast<uint32_t*>(&t);
}
__device__ __forceinline__ float bfres(float a) {
    return a - __bfloat162float(__float2bfloat16(a));
}

// ---- smem addressing ----
__device__ __forceinline__ uint32_t smem_u32(const void* p) {
    uint32_t a;
    asm("{ .reg .u64 t; cvta.to.shared.u64 t, %1; cvt.u32.u64 %0, t; }" : "=r"(a) : "l"(p));
    return a;
}
__device__ __forceinline__ uint32_t sw128(uint32_t off) { return off ^ ((off >> 3) & 0x70); }

// ---- ldmatrix / mma wrappers ----
__device__ __forceinline__ void ldsm_x4(uint32_t* r, uint32_t addr) {
    asm volatile("ldmatrix.sync.aligned.m8n8.x4.shared.b16 {%0,%1,%2,%3}, [%4];"
                 : "=r"(r[0]), "=r"(r[1]), "=r"(r[2]), "=r"(r[3]) : "r"(addr));
}
__device__ __forceinline__ void ldsm_x2(uint32_t* r, uint32_t addr) {
    asm volatile("ldmatrix.sync.aligned.m8n8.x2.shared.b16 {%0,%1}, [%2];"
                 : "=r"(r[0]), "=r"(r[1]) : "r"(addr));
}
__device__ __forceinline__ void ldsm_x2t(uint32_t* r, uint32_t addr) {
    asm volatile("ldmatrix.sync.aligned.m8n8.x2.trans.shared.b16 {%0,%1}, [%2];"
                 : "=r"(r[0]), "=r"(r[1]) : "r"(addr));
}
__device__ __forceinline__ void mma_bf16(float* d, const uint32_t* a, const uint32_t* b) {
    asm volatile(
        "mma.sync.aligned.m16n8k16.row.col.f32.bf16.bf16.f32 "
        "{%0,%1,%2,%3}, {%4,%5,%6,%7}, {%8,%9}, {%0,%1,%2,%3};"
        : "+f"(d[0]), "+f"(d[1]), "+f"(d[2]), "+f"(d[3])
        : "r"(a[0]), "r"(a[1]), "r"(a[2]), "r"(a[3]), "r"(b[0]), "r"(b[1]));
}

// pass1 smem (bytes): 4 tiles of 128 x 64 bf16 (128B rows, SW128)
constexpr int TILE_B = 128 * 128;
constexpr int SM_QHI = 0;
constexpr int SM_QLO = TILE_B;
constexpr int SM_KHI = 2 * TILE_B;
constexpr int SM_KLO = 3 * TILE_B;
constexpr int SM1_TOTAL = 4 * TILE_B;   // 65536 B

// pass2 smem (R15 layout): V hi/lo + P hi/lo (2 sub-tiles of 128r x 64c each)
constexpr int SM2_VHI = 0;
constexpr int SM2_VLO = TILE_B;
constexpr int SM2_PHI = 2 * TILE_B;   // + sub*TILE_B
constexpr int SM2_PLO = 4 * TILE_B;   // + sub*TILE_B
constexpr int SM2_TOTAL = 6 * TILE_B; // 98304 B

// ---------------------------------------------------------------------------
// Pass 1 (HMMA, unchanged passing version): scores -> SC; m/l; zero-fill.
// ---------------------------------------------------------------------------
__global__ void __launch_bounds__(128, 2)
attn_pass1(const float* __restrict__ Q, const float* __restrict__ K,
           float* __restrict__ SC)
{
    extern __shared__ char smem[];
    const uint32_t sb = smem_u32(smem);

    const int tid = threadIdx.x;
    const int lane = tid & 31;
    const int warp = tid >> 5;
    const int pid = blockIdx.x;
    const int bh = blockIdx.y;

    {
        const float4 z = make_float4(0.f, 0.f, 0.f, 0.f);
#pragma unroll
        for (int half = 0; half < 2; ++half) {
            const int qt = half ? (15 - pid) : pid;
            const int c0 = (qt + 1) * 128;
            if (c0 < S) {
                const int w4 = (S - c0) >> 2;
                const int r0 = qt * 128;
                for (int i = tid; i < 128 * w4; i += 128) {
                    const int row = i / w4;
                    const int c4 = i - row * w4;
                    *((float4*)(SC + ((size_t)bh * S + r0 + row) * S + c0 + 4 * c4)) = z;
                }
            }
        }
    }

    for (int half = 0; half < 2; ++half) {
        const int qt = half ? (15 - pid) : pid;
        const int r0 = qt * 128;

        __syncthreads();
        {
            const float* qbase = Q + ((size_t)bh * S + r0) * D;
            for (int i = tid; i < 128 * 16; i += 128) {
                int row = i >> 4, c4 = i & 15;
                float4 v = ((const float4*)(qbase + row * D))[c4];
                uint32_t off = sw128((uint32_t)(row * 128 + c4 * 8));
                *((uint2*)(smem + SM_QHI + off)) =
                    make_uint2(bf2pack(v.x, v.y), bf2pack(v.z, v.w));
                *((uint2*)(smem + SM_QLO + off)) =
                    make_uint2(bf2pack(bfres(v.x), bfres(v.y)), bf2pack(bfres(v.z), bfres(v.w)));
            }
        }

        float m[2][2], l[2][2];
#pragma unroll
        for (int a = 0; a < 2; a++)
#pragma unroll
            for (int b = 0; b < 2; b++) { m[a][b] = -1e30f; l[a][b] = 0.0f; }

        for (int kt = 0; kt <= qt; ++kt) {
            __syncthreads();
            {
                const float* kbase = K + ((size_t)bh * S + kt * 128) * D;
                for (int i = tid; i < 128 * 16; i += 128) {
                    int row = i >> 4, c4 = i & 15;
                    float4 v = ((const float4*)(kbase + row * D))[c4];
                    uint32_t off = sw128((uint32_t)(row * 128 + c4 * 8));
                    *((uint2*)(smem + SM_KHI + off)) =
                        make_uint2(bf2pack(v.x, v.y), bf2pack(v.z, v.w));
                    *((uint2*)(smem + SM_KLO + off)) =
                        make_uint2(bf2pack(bfres(v.x), bfres(v.y)),
                                   bf2pack(bfres(v.z), bfres(v.w)));
                }
            }
            __syncthreads();

            float acc[2][16][4];
#pragma unroll
            for (int mb = 0; mb < 2; mb++)
#pragma unroll
                for (int j = 0; j < 16; j++)
#pragma unroll
                    for (int x = 0; x < 4; x++) acc[mb][j][x] = 0.0f;

#pragma unroll
            for (int p = 0; p < 3; ++p) {
                const uint32_t abase = sb + ((p == 2) ? SM_QLO : SM_QHI);
                const uint32_t bbase = sb + ((p == 1) ? SM_KLO : SM_KHI);
#pragma unroll
                for (int ks = 0; ks < 4; ++ks) {
                    const int kk = 16 * ks;
                    uint32_t afrag[2][4];
#pragma unroll
                    for (int mb = 0; mb < 2; mb++) {
                        const int arow = warp * 32 + mb * 16 + (lane & 7) + ((lane >> 3) & 1) * 8;
                        const uint32_t acol = (uint32_t)(kk * 2) + (uint32_t)(lane >> 4) * 16u;
                        ldsm_x4(afrag[mb], abase + sw128((uint32_t)(arow * 128) + acol));
                    }
#pragma unroll
                    for (int j = 0; j < 16; ++j) {
                        const int brow = 8 * j + (lane & 7);
                        const uint32_t bcol = (uint32_t)(kk * 2) + ((uint32_t)(lane >> 3) & 1u) * 16u;
                        uint32_t bfrag[2];
                        ldsm_x2(bfrag, bbase + sw128((uint32_t)(brow * 128) + bcol));
                        mma_bf16(acc[0][j], afrag[0], bfrag);
                        mma_bf16(acc[1][j], afrag[1], bfrag);
                    }
                }
            }

            const bool diag = (kt == qt);
#pragma unroll
            for (int mb = 0; mb < 2; mb++) {
#pragma unroll
                for (int rg = 0; rg < 2; rg++) {
                    const int row = warp * 32 + mb * 16 + rg * 8 + (lane >> 2);
                    float sv[32];
                    float mx = -1e30f;
#pragma unroll
                    for (int j = 0; j < 16; j++) {
                        const int c0 = 8 * j + (lane & 3) * 2;
                        float s0 = acc[mb][j][2 * rg] * SCALE;
                        float s1 = acc[mb][j][2 * rg + 1] * SCALE;
                        if (diag) {
                            if (c0 > row) s0 = -1e9f;
                            if (c0 + 1 > row) s1 = -1e9f;
                        }
                        sv[2 * j] = s0;
                        sv[2 * j + 1] = s1;
                        mx = fmaxf(mx, fmaxf(s0, s1));
                    }
                    mx = fmaxf(mx, __shfl_xor_sync(0xffffffffu, mx, 1));
                    mx = fmaxf(mx, __shfl_xor_sync(0xffffffffu, mx, 2));

                    const float mn = fmaxf(m[mb][rg], mx);
                    float ps = 0.0f;
#pragma unroll
                    for (int c = 0; c < 32; c++) ps += __expf(sv[c] - mn);
                    ps += __shfl_xor_sync(0xffffffffu, ps, 1);
                    ps += __shfl_xor_sync(0xffffffffu, ps, 2);

                    l[mb][rg] = l[mb][rg] * __expf(m[mb][rg] - mn) + ps;
                    m[mb][rg] = mn;

                    float* dst = SC + ((size_t)bh * S + r0 + row) * S + kt * 128;
#pragma unroll
                    for (int j = 0; j < 16; j++)
                        *((float2*)(dst + 8 * j + (lane & 3) * 2)) =
                            make_float2(sv[2 * j], sv[2 * j + 1]);
                }
            }
        }

        if ((lane & 3) == 0) {
#pragma unroll
            for (int mb = 0; mb < 2; mb++)
#pragma unroll
                for (int rg = 0; rg < 2; rg++) {
                    const int row = warp * 32 + mb * 16 + rg * 8 + (lane >> 2);
                    g_m[bh * S + r0 + row] = m[mb][rg];
                    g_l[bh * S + r0 + row] = l[mb][rg];
                }
        }
    }
}

// ---------------------------------------------------------------------------
// Pass 2 (HMMA PV, R15 structure + 4m x 2n warp grid):
// probs -> gmem + bf16 hi/lo smem; ctx via MMA fragments.
// 256 threads = 8 warps; warp (wm, wn) owns 32 rows x 32 d.
// ---------------------------------------------------------------------------
__global__ void __launch_bounds__(256, 2)
attn_pass2(const float* __restrict__ V, float* __restrict__ SC,
           float* __restrict__ CTX)
{
    extern __shared__ char sm2[];
    const uint32_t sb = smem_u32(sm2);

    const int tid = threadIdx.x;
    const int lane = tid & 31;
    const int warp = tid >> 5;
    const int wm = warp & 3;         // m quarter (32 rows)
    const int wn = warp >> 2;        // n half (32 d)
    const int prow = tid >> 1;       // prob row 0..127
    const int psub = tid & 1;        // col half / P sub-tile
    const int pid = blockIdx.x;
    const int bh = blockIdx.y;

    for (int half = 0; half < 2; ++half) {
        const int qt = half ? (15 - pid) : pid;
        const int r0 = qt * 128;

        const float mrow = g_m[bh * S + r0 + prow];
        const float rlrow = 1.0f / g_l[bh * S + r0 + prow];

        float cacc[2][4][4];
#pragma unroll
        for (int mb = 0; mb < 2; mb++)
#pragma unroll
            for (int j = 0; j < 4; j++)
#pragma unroll
                for (int x = 0; x < 4; x++) cacc[mb][j][x] = 0.0f;

        for (int kt = 0; kt <= qt; ++kt) {
            __syncthreads();   // prior MMA done reading V/P tiles
            // Load V tile (128 k-rows x 64 d) -> bf16 hi/lo, SW128
            {
                const float* vbase = V + ((size_t)bh * S + kt * 128) * D;
                for (int i = tid; i < 128 * 16; i += 256) {
                    int row = i >> 4, c4 = i & 15;
                    float4 v = ((const float4*)(vbase + row * D))[c4];
                    uint32_t off = sw128((uint32_t)(row * 128 + c4 * 8));
                    *((uint2*)(sm2 + SM2_VHI + off)) =
                        make_uint2(bf2pack(v.x, v.y), bf2pack(v.z, v.w));
                    *((uint2*)(sm2 + SM2_VLO + off)) =
                        make_uint2(bf2pack(bfres(v.x), bfres(v.y)),
                                   bf2pack(bfres(v.z), bfres(v.w)));
                }
            }

            // Prob phase: read scores, exp, write fp32 probs + bf16 hi/lo smem
            {
                float* srow = SC + ((size_t)bh * S + r0 + prow) * S + kt * 128 + psub * 64;
                char* phidst = sm2 + SM2_PHI + psub * TILE_B;
                char* plodst = sm2 + SM2_PLO + psub * TILE_B;
#pragma unroll 4
                for (int c4 = 0; c4 < 16; ++c4) {
                    float4 s4 = ((const float4*)srow)[c4];
                    float4 p4;
                    p4.x = __expf(s4.x - mrow) * rlrow;
                    p4.y = __expf(s4.y - mrow) * rlrow;
                    p4.z = __expf(s4.z - mrow) * rlrow;
                    p4.w = __expf(s4.w - mrow) * rlrow;
                    ((float4*)srow)[c4] = p4;
                    uint32_t off = sw128((uint32_t)(prow * 128 + c4 * 8));
                    *((uint2*)(phidst + off)) =
                        make_uint2(bf2pack(p4.x, p4.y), bf2pack(p4.z, p4.w));
                    *((uint2*)(plodst + off)) =
                        make_uint2(bf2pack(bfres(p4.x), bfres(p4.y)),
                                   bf2pack(bfres(p4.z), bfres(p4.w)));
                }
            }
            __syncthreads();   // P/V tiles ready

            // PV MMA: warp (wm, wn) computes rows wm*32..+31, d cols wn*32..+31
#pragma unroll 1
            for (int ks = 0; ks < 8; ++ks) {
                const int sub = ks >> 2;
                const uint32_t kkb = (uint32_t)((ks & 3) * 32);
                uint32_t aPhi[2][4], aPlo[2][4];
#pragma unroll
                for (int mb = 0; mb < 2; mb++) {
                    const int arow = wm * 32 + mb * 16 + (lane & 7) + ((lane >> 3) & 1) * 8;
                    const uint32_t aoff =
                        sw128((uint32_t)(arow * 128) + kkb + (uint32_t)(lane >> 4) * 16u);
                    ldsm_x4(aPhi[mb], sb + SM2_PHI + sub * TILE_B + aoff);
                    ldsm_x4(aPlo[mb], sb + SM2_PLO + sub * TILE_B + aoff);
                }
                const int brow = ks * 16 + (lane & 7) + ((lane >> 3) & 1) * 8;
#pragma unroll
                for (int j = 0; j < 4; ++j) {
                    const uint32_t boff =
                        sw128((uint32_t)(brow * 128) + (uint32_t)(wn * 64 + j * 16));
                    uint32_t bhi[2], blo[2];
                    ldsm_x2t(bhi, sb + SM2_VHI + boff);
                    ldsm_x2t(blo, sb + SM2_VLO + boff);
#pragma unroll
                    for (int mb = 0; mb < 2; mb++) {
                        mma_bf16(cacc[mb][j], aPhi[mb], bhi);
                        mma_bf16(cacc[mb][j], aPlo[mb], bhi);
                        mma_bf16(cacc[mb][j], aPhi[mb], blo);
                    }
                }
            }
        }

        // Write context: rows wm*32 + mb*16 + rg*8 + lane>>2, cols wn*32 + j*8
#pragma unroll
        for (int mb = 0; mb < 2; mb++)
#pragma unroll
            for (int rg = 0; rg < 2; rg++) {
                const int row = wm * 32 + mb * 16 + rg * 8 + (lane >> 2);
                float* crow = CTX + ((size_t)bh * S + r0 + row) * D + wn * 32;
#pragma unroll
                for (int j = 0; j < 4; j++)
                    *((float2*)(crow + j * 8 + (lane & 3) * 2)) =
                        make_float2(cacc[mb][j][2 * rg], cacc[mb][j][2 * rg + 1]);
            }
    }
}

// ---------------------------------------------------------------------------
extern "C" void kernel_launch(void* const* d_in, const int* in_sizes, int n_in,
                              void* d_out, int out_size)
{
    const float* q = (const float*)d_in[0];
    const float* k = (const float*)d_in[1];
    const float* v = (const float*)d_in[2];

    float* out = (float*)d_out;
    float* ctx = out;                 // [BH, S, D]
    float* sc  = out + CTX_ELEMS;     // [BH, S, S]

    cudaFuncSetAttribute(attn_pass1, cudaFuncAttributeMaxDynamicSharedMemorySize, SM1_TOTAL);
    cudaFuncSetAttribute(attn_pass2, cudaFuncAttributeMaxDynamicSharedMemorySize, SM2_TOTAL);

    attn_pass1<<<dim3(8, BH), 128, SM1_TOTAL>>>(q, k, sc);
    attn_pass2<<<dim3(8, BH), 256, SM2_TOTAL>>>(v, sc, ctx);
}